// round 6
// baseline (speedup 1.0000x reference)
#include <cuda_runtime.h>
#include <cfloat>
#include <math.h>

#define B_   16
#define NPER 2048
#define NTOT (B_*NPER)
#define KNN  20

// ---------------- scratch (device globals; no runtime allocation) ----------
__device__ float4 g_x0[NTOT];            // [N][4]  concat(pos, x)
__device__ float  g_sn[NTOT];            // squared norms
__device__ int    g_idx[NTOT*KNN];       // [N][20] global neighbor indices
__device__ float  g_x1[NTOT*64];
__device__ float  g_x2[NTOT*64];
__device__ float  g_x3[NTOT*128];
__device__ float  g_u2[NTOT*64];         // x1 @ (W2_top - W2_bot)
__device__ float  g_y2[NTOT*64];         // x1 @ W2_bot
__device__ float  g_u3[NTOT*128];        // x2 @ (W3_top - W3_bot)
__device__ float  g_y3[NTOT*128];        // x2 @ W3_bot
__device__ float  g_out2[B_*1024];       // global max pool result

__device__ __forceinline__ void atomicMaxFloat(float* addr, float v){
    if (v >= 0.f) atomicMax((int*)addr, __float_as_int(v));
    else          atomicMin((unsigned int*)addr, (unsigned int)__float_as_int(v));
}

// ---------------- prep kernels (keep knn at profiled launch #3) ------------
__global__ __launch_bounds__(256) void x0_kernel(const float* __restrict__ pos,
                                                 const float* __restrict__ xf){
    int i = blockIdx.x*256 + threadIdx.x;
    g_x0[i] = make_float4(pos[i*3+0], pos[i*3+1], pos[i*3+2], xf[i]);
}
__global__ __launch_bounds__(256) void sn_kernel(){
    int i = blockIdx.x*256 + threadIdx.x;
    float4 p = g_x0[i];
    g_sn[i] = p.x*p.x + p.y*p.y + p.z*p.z + p.w*p.w;
}
__global__ void init_out2_kernel(){
    int t = blockIdx.x*blockDim.x + threadIdx.x;
    if (t < B_*1024) g_out2[t] = -FLT_MAX;
}

// ---------------- kNN: warp per query, distributed register top-20 ---------
// Lane t (t<20) owns slot t of the top-20. 32 candidates per step; inserts
// are warp-uniform (no 32-lane divergence union).
__global__ __launch_bounds__(512) void knn_kernel()
{
    __shared__ float4 sp[NPER];
    __shared__ float  sn[NPER];
    const unsigned FULL = 0xFFFFFFFFu;
    int b    = blockIdx.x >> 7;                 // 128 blocks per graph
    int base = b * NPER;
    for (int j = threadIdx.x; j < NPER; j += 512){
        sp[j] = g_x0[base+j];
        sn[j] = g_sn[base+j];
    }
    __syncthreads();

    int lane = threadIdx.x & 31;
    int q    = (blockIdx.x & 127)*16 + (threadIdx.x >> 5);  // 16 queries/block
    float4 p = sp[q];
    float  pn = sn[q];

    float bd = FLT_MAX;   // this lane's slot (valid for lane<20)
    int   bi = 0;
    float worst = FLT_MAX;

    for (int s = 0; s < NPER; s += 32){
        int j = s + lane;
        float4 c = sp[j];
        float d = pn + sn[j] - 2.f*(p.x*c.x + p.y*c.y + p.z*c.z + p.w*c.w);
        if (j == q) d = FLT_MAX;
        unsigned m = __ballot_sync(FULL, d < worst);
        while (m){
            int src = __ffs(m) - 1; m &= m - 1;
            float dn = __shfl_sync(FULL, d, src);
            if (dn < worst){   // uniform branch (dn, worst warp-uniform)
                unsigned wm = __ballot_sync(FULL, (lane < KNN) && (bd == worst));
                int slot = __ffs(wm) - 1;
                if (lane == slot){ bd = dn; bi = s + src; }
                float v = (lane < KNN) ? bd : -FLT_MAX;
                #pragma unroll
                for (int t = 16; t > 0; t >>= 1)
                    v = fmaxf(v, __shfl_xor_sync(FULL, v, t));
                worst = v;
            }
        }
    }
    if (lane < KNN) g_idx[(base+q)*KNN + lane] = base + bi;
}

// ---------------- EdgeConv1: fused MLP(8->64->64->64), max over K ----------
__global__ __launch_bounds__(256) void conv1_kernel(
    const float* __restrict__ w1, const float* __restrict__ b1,
    const float* __restrict__ w2, const float* __restrict__ b2,
    const float* __restrict__ w3, const float* __restrict__ b3)
{
    __shared__ float sW1 [4*64];
    __shared__ float sW1d[4*64];
    __shared__ float sW2t[64*68];
    __shared__ float sW3t[64*68];
    __shared__ float sb1[64], sb2[64], sb3[64];
    __shared__ float hbuf[8][4][64];

    for (int t = threadIdx.x; t < 64*64; t += 256){
        int c = t >> 6, o = t & 63;
        sW2t[o*68+c] = w2[t];
        sW3t[o*68+c] = w3[t];
    }
    for (int t = threadIdx.x; t < 4*64; t += 256){
        int c = t >> 6, o = t & 63;
        float top = w1[c*64+o], bot = w1[(c+4)*64+o];
        sW1[t] = bot; sW1d[t] = top - bot;
    }
    if (threadIdx.x < 64){
        sb1[threadIdx.x] = b1[threadIdx.x];
        sb2[threadIdx.x] = b2[threadIdx.x];
        sb3[threadIdx.x] = b3[threadIdx.x];
    }
    __syncthreads();

    int wd = threadIdx.x >> 5, lane = threadIdx.x & 31;
    int i  = blockIdx.x * 8 + wd;
    int o0 = lane, o1 = lane + 32;
    float4 xi = g_x0[i];
    float base0 = sb1[o0] + xi.x*sW1d[o0] + xi.y*sW1d[64+o0] + xi.z*sW1d[128+o0] + xi.w*sW1d[192+o0];
    float base1 = sb1[o1] + xi.x*sW1d[o1] + xi.y*sW1d[64+o1] + xi.z*sW1d[128+o1] + xi.w*sW1d[192+o1];
    float mx0 = -FLT_MAX, mx1 = -FLT_MAX;
    const int* ip = g_idx + i*KNN;

    for (int kg = 0; kg < 5; kg++){
        #pragma unroll
        for (int e=0;e<4;e++){
            int j = ip[kg*4+e];
            float4 xj = g_x0[j];
            float v0 = base0 + xj.x*sW1[o0] + xj.y*sW1[64+o0] + xj.z*sW1[128+o0] + xj.w*sW1[192+o0];
            float v1 = base1 + xj.x*sW1[o1] + xj.y*sW1[64+o1] + xj.z*sW1[128+o1] + xj.w*sW1[192+o1];
            hbuf[wd][e][o0] = fmaxf(v0, 0.f);
            hbuf[wd][e][o1] = fmaxf(v1, 0.f);
        }
        __syncwarp();
        float a0[4], a1[4];
        #pragma unroll
        for (int e=0;e<4;e++){ a0[e]=sb2[o0]; a1[e]=sb2[o1]; }
        #pragma unroll
        for (int c4=0;c4<16;c4++){
            float4 wv0 = *(const float4*)(sW2t + o0*68 + c4*4);
            float4 wv1 = *(const float4*)(sW2t + o1*68 + c4*4);
            #pragma unroll
            for (int e=0;e<4;e++){
                float4 h = *(const float4*)(&hbuf[wd][e][c4*4]);
                a0[e] += h.x*wv0.x + h.y*wv0.y + h.z*wv0.z + h.w*wv0.w;
                a1[e] += h.x*wv1.x + h.y*wv1.y + h.z*wv1.z + h.w*wv1.w;
            }
        }
        __syncwarp();
        #pragma unroll
        for (int e=0;e<4;e++){
            hbuf[wd][e][o0] = fmaxf(a0[e], 0.f);
            hbuf[wd][e][o1] = fmaxf(a1[e], 0.f);
        }
        __syncwarp();
        #pragma unroll
        for (int e=0;e<4;e++){ a0[e]=sb3[o0]; a1[e]=sb3[o1]; }
        #pragma unroll
        for (int c4=0;c4<16;c4++){
            float4 wv0 = *(const float4*)(sW3t + o0*68 + c4*4);
            float4 wv1 = *(const float4*)(sW3t + o1*68 + c4*4);
            #pragma unroll
            for (int e=0;e<4;e++){
                float4 h = *(const float4*)(&hbuf[wd][e][c4*4]);
                a0[e] += h.x*wv0.x + h.y*wv0.y + h.z*wv0.z + h.w*wv0.w;
                a1[e] += h.x*wv1.x + h.y*wv1.y + h.z*wv1.z + h.w*wv1.w;
            }
        }
        #pragma unroll
        for (int e=0;e<4;e++){ mx0 = fmaxf(mx0, a0[e]); mx1 = fmaxf(mx1, a1[e]); }
        __syncwarp();
    }
    g_x1[i*64+o0] = mx0;
    g_x1[i*64+o1] = mx1;
}

// ---------------- node-level GEMM: U = X@(Wt-Wb), Y = X@Wb ------------------
__device__ __forceinline__ void uy_gemm_body(
    const float* __restrict__ X,   // [N x 64]
    const float* __restrict__ W,   // [128 x OUT]
    float* __restrict__ U, float* __restrict__ Y, int OUT)
{
    __shared__ float fbuf[64*33];
    __shared__ float wbuf[32*132];
    int nbase = blockIdx.x * 64;
    int otile = blockIdx.y * 128;
    int tn = threadIdx.x & 15;
    int to = threadIdx.x >> 4;

    float acc[4][8];
    #pragma unroll
    for (int r=0;r<4;r++)
        #pragma unroll
        for (int q=0;q<8;q++) acc[r][q]=0.f;

    for (int kc=0;kc<2;kc++){
        for (int t=threadIdx.x; t<64*32; t+=256){
            int n=t>>5, kk=t&31;
            fbuf[n*33+kk] = X[(nbase+n)*64 + kc*32 + kk];
        }
        for (int t=threadIdx.x; t<32*128; t+=256){
            int kk=t>>7, oloc=t&127;
            int op = otile + oloc;
            int k  = kc*32+kk;
            wbuf[kk*132+oloc] = (op < OUT)
                ? (W[k*OUT + op] - W[(64+k)*OUT + op])
                : W[(64+k)*OUT + (op-OUT)];
        }
        __syncthreads();
        #pragma unroll 4
        for (int kk=0;kk<32;kk++){
            float f[4];
            #pragma unroll
            for (int r=0;r<4;r++) f[r] = fbuf[(to+16*r)*33+kk];
            float wv[8];
            #pragma unroll
            for (int q=0;q<8;q++) wv[q] = wbuf[kk*132 + tn + 16*q];
            #pragma unroll
            for (int r=0;r<4;r++)
                #pragma unroll
                for (int q=0;q<8;q++) acc[r][q] += f[r]*wv[q];
        }
        __syncthreads();
    }
    #pragma unroll
    for (int r=0;r<4;r++){
        int node = nbase + to + 16*r;
        #pragma unroll
        for (int q=0;q<8;q++){
            int op = otile + tn + 16*q;
            if (op < OUT) U[node*OUT + op]        = acc[r][q];
            else          Y[node*OUT + (op-OUT)]  = acc[r][q];
        }
    }
}

__global__ __launch_bounds__(256) void uy_gemm2_kernel(const float* __restrict__ W){
    uy_gemm_body(g_x1, W, g_u2, g_y2, 64);
}
__global__ __launch_bounds__(256) void uy_gemm3_kernel(const float* __restrict__ W){
    uy_gemm_body(g_x2, W, g_u3, g_y3, 128);
}

// ---------------- gather + elementwise max ----------------------------------
__global__ __launch_bounds__(256) void gathermax2_kernel(const float* __restrict__ b2){
    int wd = threadIdx.x >> 5, lane = threadIdx.x & 31;
    int i = blockIdx.x*8 + wd;
    const int* ip = g_idx + i*KNN;
    float2 mx = make_float2(-FLT_MAX, -FLT_MAX);
    #pragma unroll 5
    for (int t=0;t<KNN;t++){
        int j = ip[t];
        float2 v = *(const float2*)(g_y2 + j*64 + lane*2);
        mx.x = fmaxf(mx.x, v.x);
        mx.y = fmaxf(mx.y, v.y);
    }
    float2 u  = *(const float2*)(g_u2 + i*64 + lane*2);
    float2 bb = *(const float2*)(b2 + lane*2);
    float2 o;
    o.x = bb.x + u.x + mx.x;
    o.y = bb.y + u.y + mx.y;
    *(float2*)(g_x2 + i*64 + lane*2) = o;
}

__global__ __launch_bounds__(256) void gathermax3_kernel(const float* __restrict__ b3){
    int wd = threadIdx.x >> 5, lane = threadIdx.x & 31;
    int i = blockIdx.x*8 + wd;
    const int* ip = g_idx + i*KNN;
    float4 mx = make_float4(-FLT_MAX,-FLT_MAX,-FLT_MAX,-FLT_MAX);
    #pragma unroll 5
    for (int t=0;t<KNN;t++){
        int j = ip[t];
        float4 v = *(const float4*)(g_y3 + j*128 + lane*4);
        mx.x = fmaxf(mx.x, v.x);
        mx.y = fmaxf(mx.y, v.y);
        mx.z = fmaxf(mx.z, v.z);
        mx.w = fmaxf(mx.w, v.w);
    }
    float4 u  = *(const float4*)(g_u3 + i*128 + lane*4);
    float4 bb = *(const float4*)(b3 + lane*4);
    float4 o;
    o.x = bb.x + u.x + mx.x;
    o.y = bb.y + u.y + mx.y;
    o.z = bb.z + u.z + mx.z;
    o.w = bb.w + u.w + mx.w;
    *(float4*)(g_x3 + i*128 + lane*4) = o;
}

// ---------------- lin1 (256->1024) fused with global max pool (R4 scalar) --
__global__ __launch_bounds__(256) void lin1max_kernel(
    const float* __restrict__ l1w, const float* __restrict__ l1b)
{
    __shared__ float fbuf[64*33];
    __shared__ float wbuf[32*132];
    int g     = blockIdx.x >> 5;
    int nbase = g*NPER + (blockIdx.x & 31)*64;
    int tn = threadIdx.x & 15, to = threadIdx.x >> 4;

    for (int oc=0; oc<8; ++oc){
        float acc[4][8];
        #pragma unroll
        for (int r=0;r<4;r++)
            #pragma unroll
            for (int q=0;q<8;q++) acc[r][q]=0.f;

        for (int kc=0;kc<8;kc++){
            for (int t=threadIdx.x; t<64*32; t+=256){
                int n = t>>5, kk = t&31;
                int kglob = kc*32+kk;
                int node  = nbase + n;
                float v;
                if (kglob < 64)       v = g_x1[node*64  + kglob];
                else if (kglob < 128) v = g_x2[node*64  + (kglob-64)];
                else                  v = g_x3[node*128 + (kglob-128)];
                fbuf[n*33+kk] = v;
            }
            for (int t=threadIdx.x; t<32*128; t+=256){
                int kk = t>>7, o = t&127;
                wbuf[kk*132+o] = l1w[(kc*32+kk)*1024 + oc*128 + o];
            }
            __syncthreads();
            #pragma unroll 4
            for (int kk=0;kk<32;kk++){
                float f0 = fbuf[(tn +  0)*33+kk];
                float f1 = fbuf[(tn + 16)*33+kk];
                float f2 = fbuf[(tn + 32)*33+kk];
                float f3 = fbuf[(tn + 48)*33+kk];
                float wv[8];
                #pragma unroll
                for (int q=0;q<8;q++) wv[q] = wbuf[kk*132 + to + 16*q];
                #pragma unroll
                for (int q=0;q<8;q++){
                    acc[0][q] += f0*wv[q];
                    acc[1][q] += f1*wv[q];
                    acc[2][q] += f2*wv[q];
                    acc[3][q] += f3*wv[q];
                }
            }
            __syncthreads();
        }
        float m[8];
        #pragma unroll
        for (int q=0;q<8;q++)
            m[q] = fmaxf(fmaxf(acc[0][q],acc[1][q]), fmaxf(acc[2][q],acc[3][q]));
        #pragma unroll
        for (int q=0;q<8;q++) wbuf[tn*128 + to + 16*q] = m[q];
        __syncthreads();
        if (threadIdx.x < 128){
            int c = threadIdx.x;
            float v = wbuf[c];
            #pragma unroll
            for (int t=1;t<16;t++) v = fmaxf(v, wbuf[t*128+c]);
            v += l1b[oc*128+c];
            atomicMaxFloat(&g_out2[g*1024 + oc*128 + c], v);
        }
        __syncthreads();
    }
}

// ---------------- head: MLP(1024->512->256->10) + log_softmax --------------
__global__ __launch_bounds__(256) void head_kernel(
    const float* __restrict__ m1w, const float* __restrict__ m1b,
    const float* __restrict__ m2w, const float* __restrict__ m2b,
    const float* __restrict__ m3w, const float* __restrict__ m3b,
    float* __restrict__ out)
{
    __shared__ float v[1024];
    __shared__ float h1[512];
    __shared__ float h2[256];
    __shared__ float z[10];
    int g = blockIdx.x;
    for (int t=threadIdx.x; t<1024; t+=256) v[t] = g_out2[g*1024+t];
    __syncthreads();
    #pragma unroll
    for (int oo=0;oo<2;oo++){
        int o = threadIdx.x + oo*256;
        float a = m1b[o];
        #pragma unroll 4
        for (int k=0;k<1024;k++) a += v[k]*m1w[k*512+o];
        h1[o] = fmaxf(a, 0.f);
    }
    __syncthreads();
    {
        int o = threadIdx.x;
        float a = m2b[o];
        #pragma unroll 4
        for (int k=0;k<512;k++) a += h1[k]*m2w[k*256+o];
        h2[o] = fmaxf(a, 0.f);
    }
    __syncthreads();
    if (threadIdx.x < 10){
        float a = m3b[threadIdx.x];
        for (int k=0;k<256;k++) a += h2[k]*m3w[k*10+threadIdx.x];
        z[threadIdx.x] = a;
    }
    __syncthreads();
    if (threadIdx.x == 0){
        float m = -FLT_MAX;
        for (int c=0;c<10;c++) m = fmaxf(m, z[c]);
        float s = 0.f;
        for (int c=0;c<10;c++) s += expf(z[c]-m);
        float l = logf(s);
        for (int c=0;c<10;c++) out[g*10+c] = z[c]-m-l;
    }
}

// ---------------- launch ----------------------------------------------------
extern "C" void kernel_launch(void* const* d_in, const int* in_sizes, int n_in,
                              void* d_out, int out_size)
{
    const float* pos  = (const float*)d_in[0];
    const float* xf   = (const float*)d_in[1];
    const float* c1w1 = (const float*)d_in[3];
    const float* c1b1 = (const float*)d_in[4];
    const float* c1w2 = (const float*)d_in[5];
    const float* c1b2 = (const float*)d_in[6];
    const float* c1w3 = (const float*)d_in[7];
    const float* c1b3 = (const float*)d_in[8];
    const float* c2w  = (const float*)d_in[9];
    const float* c2b  = (const float*)d_in[10];
    const float* c3w  = (const float*)d_in[11];
    const float* c3b  = (const float*)d_in[12];
    const float* l1w  = (const float*)d_in[13];
    const float* l1b  = (const float*)d_in[14];
    const float* m1w  = (const float*)d_in[15];
    const float* m1b  = (const float*)d_in[16];
    const float* m2w  = (const float*)d_in[17];
    const float* m2b  = (const float*)d_in[18];
    const float* m3w  = (const float*)d_in[19];
    const float* m3b  = (const float*)d_in[20];
    float* out = (float*)d_out;

    x0_kernel<<<NTOT/256, 256>>>(pos, xf);          // launch 0
    sn_kernel<<<NTOT/256, 256>>>();                 // launch 1
    init_out2_kernel<<<(B_*1024+255)/256, 256>>>(); // launch 2
    knn_kernel<<<NTOT/16, 512>>>();                 // launch 3 (profiled)
    conv1_kernel<<<NTOT/8, 256>>>(c1w1,c1b1,c1w2,c1b2,c1w3,c1b3);
    uy_gemm2_kernel<<<dim3(NTOT/64, 1), 256>>>(c2w);
    gathermax2_kernel<<<NTOT/8, 256>>>(c2b);
    uy_gemm3_kernel<<<dim3(NTOT/64, 2), 256>>>(c3w);
    gathermax3_kernel<<<NTOT/8, 256>>>(c3b);
    lin1max_kernel<<<B_*32, 256>>>(l1w, l1b);
    head_kernel<<<B_, 256>>>(m1w,m1b,m2w,m2b,m3w,m3b,out);
}